// round 16
// baseline (speedup 1.0000x reference)
#include <cuda_runtime.h>
#include <cuda_bf16.h>
#include <cstdint>

#define N_NODES 20000
#define N_EDGES 640000
#define C_IN    128
#define K_FOLDS 8
#define FILTERS 128
#define KTOT    (K_FOLDS * C_IN)   // 1024

#define ROW_SPLIT 9984             // multiple of 64 (gemm tile) and 8 (gather block)

typedef unsigned long long ull;

// Scratch
__device__ __nv_bfloat16 g_Yh[(size_t)N_NODES * KTOT];   // 41 MB
__device__ __nv_bfloat16 g_Yl[(size_t)N_NODES * KTOT];   // 41 MB
__device__ __nv_bfloat16 g_Wth[FILTERS * KTOT];          // Wt hi: [f][k*128+c]
__device__ __nv_bfloat16 g_Wtl[FILTERS * KTOT];          // Wt lo
__device__ int   g_hist[N_NODES];
__device__ int   g_start[N_NODES + 1];
__device__ int   g_cur[N_NODES];
__device__ int   g_scol[N_EDGES];
__device__ float g_w8[(size_t)N_EDGES * K_FOLDS];

#define PACK2(d, x, y)   asm("mov.b64 %0, {%1,%2};" : "=l"(d) : "f"(x), "f"(y))
#define UNPACK2(x, y, d) asm("mov.b64 {%0,%1}, %2;" : "=f"(x), "=f"(y) : "l"(d))
#define FFMA2(acc, a, b) asm("fma.rn.f32x2 %0, %1, %2, %0;" : "+l"(acc) : "l"(a), "l"(b))

#define SW128(o) ((o) ^ (((o) >> 3) & 0x70))

static __device__ __forceinline__ uint32_t smem_u32(const void* p) {
    uint32_t a;
    asm("{ .reg .u64 t; cvta.to.shared.u64 t, %1; cvt.u32.u64 %0, t; }" : "=r"(a) : "l"(p));
    return a;
}

// ---------------------------------------------------------------------------
// prep_w + zero_hist fused
// ---------------------------------------------------------------------------
__global__ __launch_bounds__(256) void prep_w(const float* __restrict__ Wall) {
    const int i = blockIdx.x * 256 + threadIdx.x;
    if (i < N_NODES) g_hist[i] = 0;
    if (i >= K_FOLDS * C_IN * FILTERS) return;
    const int f = i & 127;
    const int c = (i >> 7) & 127;
    const int k = i >> 14;
    const float v = Wall[i];
    const __nv_bfloat16 h = __float2bfloat16(v);
    const __nv_bfloat16 l = __float2bfloat16(v - __bfloat162float(h));
    const int o = f * KTOT + k * C_IN + c;
    g_Wth[o] = h;
    g_Wtl[o] = l;
}

__global__ __launch_bounds__(256) void hist_rows(const int* __restrict__ idx) {
    const int e = blockIdx.x * 256 + threadIdx.x;
    const int row = reinterpret_cast<const int2*>(idx)[e].x;
    atomicAdd(&g_hist[row], 1);
}

// ---------------------------------------------------------------------------
// scan_hist: smem-staged
// ---------------------------------------------------------------------------
#define BINS_PER_THREAD 20
#define SCAN_SMEM (N_NODES * 4)

__global__ __launch_bounds__(1024) void scan_hist() {
    extern __shared__ int s[];
    const int tid  = threadIdx.x;
    const int lane = tid & 31;
    const int wid  = tid >> 5;

    int4* s4 = reinterpret_cast<int4*>(s);
    const int4* g4 = reinterpret_cast<const int4*>(g_hist);
    for (int i = tid; i < N_NODES / 4; i += 1024) s4[i] = g4[i];
    __syncthreads();

    const int base = tid * BINS_PER_THREAD;
    int local[BINS_PER_THREAD];
    int sum = 0;
#pragma unroll
    for (int i = 0; i < BINS_PER_THREAD; i++) {
        const int b = base + i;
        const int v = (b < N_NODES) ? s[b] : 0;
        local[i] = v;
        sum += v;
    }
    int x = sum;
#pragma unroll
    for (int off = 1; off < 32; off <<= 1) {
        int t = __shfl_up_sync(0xffffffffu, x, off);
        if (lane >= off) x += t;
    }
    __shared__ int wsum[32];
    if (lane == 31) wsum[wid] = x;
    __syncthreads();
    if (wid == 0) {
        int w = wsum[lane];
#pragma unroll
        for (int off = 1; off < 32; off <<= 1) {
            int t = __shfl_up_sync(0xffffffffu, w, off);
            if (lane >= off) w += t;
        }
        wsum[lane] = w;
    }
    __syncthreads();
    int run = x - sum + (wid > 0 ? wsum[wid - 1] : 0);
#pragma unroll
    for (int i = 0; i < BINS_PER_THREAD; i++) {
        const int b = base + i;
        if (b < N_NODES) {
            s[b] = run;
            run += local[i];
        }
    }
    __syncthreads();

    int4* st4 = reinterpret_cast<int4*>(g_start);
    int4* cu4 = reinterpret_cast<int4*>(g_cur);
    for (int i = tid; i < N_NODES / 4; i += 1024) {
        const int4 v = s4[i];
        st4[i] = v;
        cu4[i] = v;
    }
    if (tid == 0) g_start[N_NODES] = N_EDGES;
}

// ---------------------------------------------------------------------------
// scatter_sort
// ---------------------------------------------------------------------------
__global__ __launch_bounds__(256) void scatter_sort(const int* __restrict__ idx,
                                                    const float* __restrict__ ef) {
    const int e = blockIdx.x * 256 + threadIdx.x;
    const int2 rc = reinterpret_cast<const int2*>(idx)[e];
    const int pos = atomicAdd(&g_cur[rc.x], 1);
    g_scol[pos] = rc.y;
    float w[K_FOLDS];
#pragma unroll
    for (int k = 0; k < K_FOLDS; k++) w[k] = ef[(size_t)k * N_EDGES + e];
    float4* wp = reinterpret_cast<float4*>(g_w8 + (size_t)pos * K_FOLDS);
    wp[0] = make_float4(w[0], w[1], w[2], w[3]);
    wp[1] = make_float4(w[4], w[5], w[6], w[7]);
}

// ---------------------------------------------------------------------------
// row_gather: R15 body, parameterized by row range [row0, row_lim).
// ---------------------------------------------------------------------------
__global__ __launch_bounds__(256, 4) void row_gather(const float* __restrict__ X,
                                                     int row0, int row_lim) {
    const int r    = row0 + blockIdx.x * 8 + (threadIdx.x >> 5);
    const int lane = threadIdx.x & 31;
    if (r >= row_lim) return;

    const int beg = g_start[r];
    const int end = g_start[r + 1];

    ull acc[K_FOLDS][2];
#pragma unroll
    for (int k = 0; k < K_FOLDS; k++) { acc[k][0] = 0ull; acc[k][1] = 0ull; }

    int e = beg;
    for (; e + 3 < end; e += 4) {
        int   cc[4];
        float4 xv[4];
#pragma unroll
        for (int j = 0; j < 4; j++) cc[j] = g_scol[e + j];
#pragma unroll
        for (int j = 0; j < 4; j++)
            xv[j] = reinterpret_cast<const float4*>(X + (size_t)cc[j] * C_IN)[lane];
        const float4* wp = reinterpret_cast<const float4*>(g_w8 + (size_t)e * K_FOLDS);
        float4 wv[8];
#pragma unroll
        for (int j = 0; j < 8; j++) wv[j] = wp[j];

        ull xlo[4], xhi[4];
#pragma unroll
        for (int j = 0; j < 4; j++) {
            PACK2(xlo[j], xv[j].x, xv[j].y);
            PACK2(xhi[j], xv[j].z, xv[j].w);
        }
        const float* wf = reinterpret_cast<const float*>(wv);
#pragma unroll
        for (int k = 0; k < K_FOLDS; k++) {
#pragma unroll
            for (int j = 0; j < 4; j++) {
                const float w = wf[j * 8 + k];
                ull wk;
                PACK2(wk, w, w);
                FFMA2(acc[k][0], wk, xlo[j]);
                FFMA2(acc[k][1], wk, xhi[j]);
            }
        }
    }
    for (; e < end; ++e) {
        const int c0 = g_scol[e];
        const float4 xv0 = reinterpret_cast<const float4*>(X + (size_t)c0 * C_IN)[lane];
        const float4* wp = reinterpret_cast<const float4*>(g_w8 + (size_t)e * K_FOLDS);
        const float4 wa0 = wp[0], wa1 = wp[1];
        const float wa[K_FOLDS] = {wa0.x, wa0.y, wa0.z, wa0.w, wa1.x, wa1.y, wa1.z, wa1.w};
        ull x0lo, x0hi;
        PACK2(x0lo, xv0.x, xv0.y); PACK2(x0hi, xv0.z, xv0.w);
#pragma unroll
        for (int k = 0; k < K_FOLDS; k++) {
            ull wk0;
            PACK2(wk0, wa[k], wa[k]);
            FFMA2(acc[k][0], wk0, x0lo);
            FFMA2(acc[k][1], wk0, x0hi);
        }
    }

    __nv_bfloat162* yh = reinterpret_cast<__nv_bfloat162*>(g_Yh + (size_t)r * KTOT);
    __nv_bfloat162* yl = reinterpret_cast<__nv_bfloat162*>(g_Yl + (size_t)r * KTOT);
#pragma unroll
    for (int k = 0; k < K_FOLDS; k++) {
        float v[4];
        UNPACK2(v[0], v[1], acc[k][0]);
        UNPACK2(v[2], v[3], acc[k][1]);
        __nv_bfloat16 h[4], l[4];
#pragma unroll
        for (int j = 0; j < 4; j++) {
            h[j] = __float2bfloat16(v[j]);
            l[j] = __float2bfloat16(v[j] - __bfloat162float(h[j]));
        }
        const int o = k * (C_IN / 2) + lane * 2;
        yh[o]     = __halves2bfloat162(h[0], h[1]);
        yh[o + 1] = __halves2bfloat162(h[2], h[3]);
        yl[o]     = __halves2bfloat162(l[0], l[1]);
        yl[o + 1] = __halves2bfloat162(l[2], l[3]);
    }
}

// ---------------------------------------------------------------------------
// gemm_mma (R9 config), parameterized by tile offset mb0.
// ---------------------------------------------------------------------------
#define STG_BYTES 49152
#define SM_AH 0
#define SM_AL 8192
#define SM_BH 16384
#define SM_BL 32768
#define GEMM_SMEM (2 * STG_BYTES)

#define CPA(dst, src) asm volatile("cp.async.cg.shared.global [%0], [%1], 16;" \
                                   :: "r"(dst), "l"(src) : "memory")
#define CPC()  asm volatile("cp.async.commit_group;" ::: "memory")
#define CPW1() asm volatile("cp.async.wait_group 1;" ::: "memory")
#define CPW0() asm volatile("cp.async.wait_group 0;" ::: "memory")

#define LDSM4(r, addr)                                                            \
    asm volatile("ldmatrix.sync.aligned.m8n8.x4.shared.b16 {%0,%1,%2,%3}, [%4];"  \
        : "=r"((r)[0]), "=r"((r)[1]), "=r"((r)[2]), "=r"((r)[3]) : "r"(addr))

#define MMA_BF16(c, a, b0, b1)                                                    \
    asm volatile("mma.sync.aligned.m16n8k16.row.col.f32.bf16.bf16.f32 "           \
        "{%0,%1,%2,%3}, {%4,%5,%6,%7}, {%8,%9}, {%0,%1,%2,%3};"                   \
        : "+f"((c)[0]), "+f"((c)[1]), "+f"((c)[2]), "+f"((c)[3])                  \
        : "r"((a)[0]), "r"((a)[1]), "r"((a)[2]), "r"((a)[3]), "r"(b0), "r"(b1))

__global__ __launch_bounds__(256, 2) void gemm_mma(const float* __restrict__ bias,
                                                   float* __restrict__ out, int mb0) {
    extern __shared__ char dynsm[];
    __shared__ float s_bias[FILTERS];

    const int tid  = threadIdx.x;
    const int lane = tid & 31;
    const int wid  = tid >> 5;
    const int mb   = mb0 + blockIdx.x;

    if (tid < FILTERS) s_bias[tid] = bias[tid];

    const int wm = wid >> 2;
    const int wn = wid & 3;

    const uint32_t smbase = smem_u32(dynsm);

    const int ra = tid >> 2;
    const int ca = (tid & 3) * 32;
    const int rb = tid >> 1;
    const int cbb = (tid & 1) * 64;
    const int ga_row = min(mb * 64 + ra, N_NODES - 1);
    const char* gYh = reinterpret_cast<const char*>(g_Yh + (size_t)ga_row * KTOT);
    const char* gYl = reinterpret_cast<const char*>(g_Yl + (size_t)ga_row * KTOT);
    const char* gWh = reinterpret_cast<const char*>(g_Wth + (size_t)rb * KTOT);
    const char* gWl = reinterpret_cast<const char*>(g_Wtl + (size_t)rb * KTOT);
    const uint32_t saoff0 = SW128((uint32_t)(ra * 128 + ca));
    const uint32_t saoff1 = SW128((uint32_t)(ra * 128 + ca + 16));
    uint32_t sboff[4];
#pragma unroll
    for (int i = 0; i < 4; i++) sboff[i] = SW128((uint32_t)(rb * 128 + cbb + i * 16));

    const int trow = lane & 7;
    const int bit3 = (lane >> 3) & 1;
    const int bit4 = (lane >> 4) & 1;
    const int am60 = (trow << 4) & 0x60;
    const int am10 = (trow << 4) & 0x10;
    const int arow = trow + bit3 * 8;
    const int acol0 = (bit4 * 16) ^ am10;
    const int brow = trow + bit4 * 8;
    const int bcol0 = (bit3 * 16) ^ am10;

    uint32_t aoff[2], boff[2];
#pragma unroll
    for (int mi = 0; mi < 2; mi++)
        aoff[mi] = (uint32_t)((wm * 32 + mi * 16 + arow) * 128 + acol0);
#pragma unroll
    for (int nj = 0; nj < 2; nj++)
        boff[nj] = (uint32_t)((wn * 32 + nj * 16 + brow) * 128 + bcol0);

    float acc[2][4][4];
#pragma unroll
    for (int mi = 0; mi < 2; mi++)
#pragma unroll
        for (int ni = 0; ni < 4; ni++)
#pragma unroll
            for (int j = 0; j < 4; j++) acc[mi][ni][j] = 0.0f;

    {
        const uint32_t sb = smbase;
        CPA(sb + SM_AH + saoff0, gYh + ca);
        CPA(sb + SM_AH + saoff1, gYh + ca + 16);
        CPA(sb + SM_AL + saoff0, gYl + ca);
        CPA(sb + SM_AL + saoff1, gYl + ca + 16);
#pragma unroll
        for (int i = 0; i < 4; i++) {
            CPA(sb + SM_BH + sboff[i], gWh + cbb + i * 16);
            CPA(sb + SM_BL + sboff[i], gWl + cbb + i * 16);
        }
        CPC();
    }

    for (int s = 0; s < 16; ++s) {
        if (s < 15) {
            const uint32_t sb = smbase + (uint32_t)(((s + 1) & 1) * STG_BYTES);
            const int kb = (s + 1) * 128;
            CPA(sb + SM_AH + saoff0, gYh + kb + ca);
            CPA(sb + SM_AH + saoff1, gYh + kb + ca + 16);
            CPA(sb + SM_AL + saoff0, gYl + kb + ca);
            CPA(sb + SM_AL + saoff1, gYl + kb + ca + 16);
#pragma unroll
            for (int i = 0; i < 4; i++) {
                CPA(sb + SM_BH + sboff[i], gWh + kb + cbb + i * 16);
                CPA(sb + SM_BL + sboff[i], gWl + kb + cbb + i * 16);
            }
            CPC();
            CPW1();
        } else {
            CPW0();
        }
        __syncthreads();

        const uint32_t cb = smbase + (uint32_t)((s & 1) * STG_BYTES);
        const uint32_t sAh = cb + SM_AH, sAl = cb + SM_AL;
        const uint32_t sBh = cb + SM_BH, sBl = cb + SM_BL;

#pragma unroll
        for (int ks = 0; ks < 4; ++ks) {
            const uint32_t kx = (uint32_t)((ks * 32) ^ am60);
            uint32_t ah[2][4], al[2][4], bh[2][4], bl[2][4];
            LDSM4(ah[0], sAh + aoff[0] + kx);
            LDSM4(ah[1], sAh + aoff[1] + kx);
            LDSM4(al[0], sAl + aoff[0] + kx);
            LDSM4(al[1], sAl + aoff[1] + kx);
            LDSM4(bh[0], sBh + boff[0] + kx);
            LDSM4(bh[1], sBh + boff[1] + kx);
            LDSM4(bl[0], sBl + boff[0] + kx);
            LDSM4(bl[1], sBl + boff[1] + kx);
#pragma unroll
            for (int ni = 0; ni < 4; ++ni) {
                const uint32_t b0h = bh[ni >> 1][(ni & 1) * 2];
                const uint32_t b1h = bh[ni >> 1][(ni & 1) * 2 + 1];
                const uint32_t b0l = bl[ni >> 1][(ni & 1) * 2];
                const uint32_t b1l = bl[ni >> 1][(ni & 1) * 2 + 1];
                MMA_BF16(acc[0][ni], ah[0], b0h, b1h);
                MMA_BF16(acc[1][ni], ah[1], b0h, b1h);
                MMA_BF16(acc[0][ni], ah[0], b0l, b1l);
                MMA_BF16(acc[1][ni], ah[1], b0l, b1l);
                MMA_BF16(acc[0][ni], al[0], b0h, b1h);
                MMA_BF16(acc[1][ni], al[1], b0h, b1h);
            }
        }
        __syncthreads();
    }

    const int g   = lane >> 2;
    const int tig = lane & 3;
#pragma unroll
    for (int mi = 0; mi < 2; ++mi) {
        const int r0 = mb * 64 + wm * 32 + mi * 16 + g;
#pragma unroll
        for (int ni = 0; ni < 4; ++ni) {
            const int c0 = wn * 32 + ni * 8 + tig * 2;
            const float2 bb = *reinterpret_cast<const float2*>(&s_bias[c0]);
            if (r0 < N_NODES) {
                float2 v = make_float2(acc[mi][ni][0] + bb.x, acc[mi][ni][1] + bb.y);
                *reinterpret_cast<float2*>(out + (size_t)r0 * FILTERS + c0) = v;
            }
            if (r0 + 8 < N_NODES) {
                float2 v = make_float2(acc[mi][ni][2] + bb.x, acc[mi][ni][3] + bb.y);
                *reinterpret_cast<float2*>(out + (size_t)(r0 + 8) * FILTERS + c0) = v;
            }
        }
    }
}

// ---------------------------------------------------------------------------
// Launch: fork gemm chunk A onto a side stream to overlap with gather chunk B.
// Stream/events are created lazily on the first (non-captured correctness)
// call; the captured graph contains identical work every call.
// ---------------------------------------------------------------------------
extern "C" void kernel_launch(void* const* d_in, const int* in_sizes, int n_in,
                              void* d_out, int out_size) {
    const float* X    = (const float*)d_in[0];   // node_features (20000,128)
    const float* ef   = (const float*)d_in[1];   // edge_features (8,640000)
    const float* Wall = (const float*)d_in[2];   // kernel (8,128,128)
    const float* bias = (const float*)d_in[3];   // bias (128,)
    const int*   idx  = (const int*)d_in[4];     // indices (640000,2) int32
    float*       out  = (float*)d_out;           // (20000,128)

    static cudaStream_t s1 = [] {
        cudaStream_t s;
        cudaStreamCreateWithFlags(&s, cudaStreamNonBlocking);
        return s;
    }();
    static cudaEvent_t evA = [] {
        cudaEvent_t e;
        cudaEventCreateWithFlags(&e, cudaEventDisableTiming);
        return e;
    }();
    static cudaEvent_t evJ = [] {
        cudaEvent_t e;
        cudaEventCreateWithFlags(&e, cudaEventDisableTiming);
        return e;
    }();
    static bool attr_done = [] {
        cudaFuncSetAttribute(gemm_mma, cudaFuncAttributeMaxDynamicSharedMemorySize, GEMM_SMEM);
        cudaFuncSetAttribute(scan_hist, cudaFuncAttributeMaxDynamicSharedMemorySize, SCAN_SMEM);
        return true;
    }();
    (void)attr_done;

    prep_w<<<(K_FOLDS * C_IN * FILTERS + 255) / 256, 256>>>(Wall);
    hist_rows<<<N_EDGES / 256, 256>>>(idx);
    scan_hist<<<1, 1024, SCAN_SMEM>>>();
    scatter_sort<<<N_EDGES / 256, 256>>>(idx, ef);

    // gather chunk A: rows [0, ROW_SPLIT)
    row_gather<<<ROW_SPLIT / 8, 256>>>(X, 0, ROW_SPLIT);

    // fork: gemm chunk A on s1 (depends on gather A + prep_w, both done on stream 0)
    cudaEventRecord(evA, 0);
    cudaStreamWaitEvent(s1, evA, 0);
    gemm_mma<<<ROW_SPLIT / 64, 256, GEMM_SMEM, s1>>>(bias, out, 0);
    cudaEventRecord(evJ, s1);

    // meanwhile on stream 0: gather chunk B, then gemm chunk B
    row_gather<<<(N_NODES - ROW_SPLIT + 7) / 8, 256>>>(X, ROW_SPLIT, N_NODES);
    gemm_mma<<<(N_NODES - ROW_SPLIT + 63) / 64, 256, GEMM_SMEM>>>(bias, out, ROW_SPLIT / 64);

    // join: stream 0 (graph tail) waits for gemm chunk A
    cudaStreamWaitEvent(0, evJ, 0);
}

// round 17
// speedup vs baseline: 1.0715x; 1.0715x over previous
#include <cuda_runtime.h>
#include <cuda_bf16.h>
#include <cstdint>

#define N_NODES 20000
#define N_EDGES 640000
#define C_IN    128
#define K_FOLDS 8
#define FILTERS 128
#define KTOT    (K_FOLDS * C_IN)   // 1024

typedef unsigned long long ull;

// Scratch
__device__ __nv_bfloat16 g_Yh[(size_t)N_NODES * KTOT];   // 41 MB
__device__ __nv_bfloat16 g_Yl[(size_t)N_NODES * KTOT];   // 41 MB
__device__ __nv_bfloat16 g_Wth[FILTERS * KTOT];          // Wt hi: [f][k*128+c]
__device__ __nv_bfloat16 g_Wtl[FILTERS * KTOT];          // Wt lo
__device__ int   g_hist[N_NODES];     // zero at load (BSS); re-zeroed by scan_hist
__device__ int   g_start[N_NODES + 1];
__device__ int   g_cur[N_NODES];
__device__ int   g_scol[N_EDGES];
__device__ float g_w8[(size_t)N_EDGES * K_FOLDS];

#define PACK2(d, x, y)   asm("mov.b64 %0, {%1,%2};" : "=l"(d) : "f"(x), "f"(y))
#define UNPACK2(x, y, d) asm("mov.b64 {%0,%1}, %2;" : "=f"(x), "=f"(y) : "l"(d))
#define FFMA2(acc, a, b) asm("fma.rn.f32x2 %0, %1, %2, %0;" : "+l"(acc) : "l"(a), "l"(b))

#define SW128(o) ((o) ^ (((o) >> 3) & 0x70))

static __device__ __forceinline__ uint32_t smem_u32(const void* p) {
    uint32_t a;
    asm("{ .reg .u64 t; cvta.to.shared.u64 t, %1; cvt.u32.u64 %0, t; }" : "=r"(a) : "l"(p));
    return a;
}

// ---------------------------------------------------------------------------
// hist_prep: fused W bf16-split transpose + per-edge row histogram.
// g_hist is all-zero on entry (BSS at load; scan_hist restores the invariant).
// ---------------------------------------------------------------------------
__global__ __launch_bounds__(256) void hist_prep(const int* __restrict__ idx,
                                                 const float* __restrict__ Wall) {
    const int i = blockIdx.x * 256 + threadIdx.x;
    const int row = reinterpret_cast<const int2*>(idx)[i].x;
    atomicAdd(&g_hist[row], 1);
    if (i < K_FOLDS * C_IN * FILTERS) {
        const int f = i & 127;
        const int c = (i >> 7) & 127;
        const int k = i >> 14;
        const float v = Wall[i];
        const __nv_bfloat16 h = __float2bfloat16(v);
        const __nv_bfloat16 l = __float2bfloat16(v - __bfloat162float(h));
        const int o = f * KTOT + k * C_IN + c;
        g_Wth[o] = h;
        g_Wtl[o] = l;
    }
}

// ---------------------------------------------------------------------------
// scan_hist: smem-staged scan; restores g_hist to zero for the next call.
// ---------------------------------------------------------------------------
#define BINS_PER_THREAD 20
#define SCAN_SMEM (N_NODES * 4)

__global__ __launch_bounds__(1024) void scan_hist() {
    extern __shared__ int s[];
    const int tid  = threadIdx.x;
    const int lane = tid & 31;
    const int wid  = tid >> 5;

    int4* s4 = reinterpret_cast<int4*>(s);
    int4* g4 = reinterpret_cast<int4*>(g_hist);
    for (int i = tid; i < N_NODES / 4; i += 1024) s4[i] = g4[i];
    __syncthreads();

    const int base = tid * BINS_PER_THREAD;
    int local[BINS_PER_THREAD];
    int sum = 0;
#pragma unroll
    for (int i = 0; i < BINS_PER_THREAD; i++) {
        const int b = base + i;
        const int v = (b < N_NODES) ? s[b] : 0;
        local[i] = v;
        sum += v;
    }
    int x = sum;
#pragma unroll
    for (int off = 1; off < 32; off <<= 1) {
        int t = __shfl_up_sync(0xffffffffu, x, off);
        if (lane >= off) x += t;
    }
    __shared__ int wsum[32];
    if (lane == 31) wsum[wid] = x;
    __syncthreads();
    if (wid == 0) {
        int w = wsum[lane];
#pragma unroll
        for (int off = 1; off < 32; off <<= 1) {
            int t = __shfl_up_sync(0xffffffffu, w, off);
            if (lane >= off) w += t;
        }
        wsum[lane] = w;
    }
    __syncthreads();
    int run = x - sum + (wid > 0 ? wsum[wid - 1] : 0);
#pragma unroll
    for (int i = 0; i < BINS_PER_THREAD; i++) {
        const int b = base + i;
        if (b < N_NODES) {
            s[b] = run;
            run += local[i];
        }
    }
    __syncthreads();

    int4* st4 = reinterpret_cast<int4*>(g_start);
    int4* cu4 = reinterpret_cast<int4*>(g_cur);
    const int4 z = make_int4(0, 0, 0, 0);
    for (int i = tid; i < N_NODES / 4; i += 1024) {
        const int4 v = s4[i];
        st4[i] = v;
        cu4[i] = v;
        g4[i]  = z;       // restore the all-zero invariant for the next call
    }
    if (tid == 0) g_start[N_NODES] = N_EDGES;
}

// ---------------------------------------------------------------------------
// scatter_sort: cols + weights into row-sorted order.  (R9/R15 version)
// ---------------------------------------------------------------------------
__global__ __launch_bounds__(256) void scatter_sort(const int* __restrict__ idx,
                                                    const float* __restrict__ ef) {
    const int e = blockIdx.x * 256 + threadIdx.x;
    const int2 rc = reinterpret_cast<const int2*>(idx)[e];
    const int pos = atomicAdd(&g_cur[rc.x], 1);
    g_scol[pos] = rc.y;
    float w[K_FOLDS];
#pragma unroll
    for (int k = 0; k < K_FOLDS; k++) w[k] = ef[(size_t)k * N_EDGES + e];
    float4* wp = reinterpret_cast<float4*>(g_w8 + (size_t)pos * K_FOLDS);
    wp[0] = make_float4(w[0], w[1], w[2], w[3]);
    wp[1] = make_float4(w[4], w[5], w[6], w[7]);
}

// ---------------------------------------------------------------------------
// row_gather: R15 champion version (exact R9 body, launch_bounds(256,4)).
// ---------------------------------------------------------------------------
__global__ __launch_bounds__(256, 4) void row_gather(const float* __restrict__ X) {
    const int r    = blockIdx.x * 8 + (threadIdx.x >> 5);
    const int lane = threadIdx.x & 31;
    if (r >= N_NODES) return;

    const int beg = g_start[r];
    const int end = g_start[r + 1];

    ull acc[K_FOLDS][2];
#pragma unroll
    for (int k = 0; k < K_FOLDS; k++) { acc[k][0] = 0ull; acc[k][1] = 0ull; }

    int e = beg;
    for (; e + 3 < end; e += 4) {
        int   cc[4];
        float4 xv[4];
#pragma unroll
        for (int j = 0; j < 4; j++) cc[j] = g_scol[e + j];
#pragma unroll
        for (int j = 0; j < 4; j++)
            xv[j] = reinterpret_cast<const float4*>(X + (size_t)cc[j] * C_IN)[lane];
        const float4* wp = reinterpret_cast<const float4*>(g_w8 + (size_t)e * K_FOLDS);
        float4 wv[8];
#pragma unroll
        for (int j = 0; j < 8; j++) wv[j] = wp[j];

        ull xlo[4], xhi[4];
#pragma unroll
        for (int j = 0; j < 4; j++) {
            PACK2(xlo[j], xv[j].x, xv[j].y);
            PACK2(xhi[j], xv[j].z, xv[j].w);
        }
        const float* wf = reinterpret_cast<const float*>(wv);
#pragma unroll
        for (int k = 0; k < K_FOLDS; k++) {
#pragma unroll
            for (int j = 0; j < 4; j++) {
                const float w = wf[j * 8 + k];
                ull wk;
                PACK2(wk, w, w);
                FFMA2(acc[k][0], wk, xlo[j]);
                FFMA2(acc[k][1], wk, xhi[j]);
            }
        }
    }
    for (; e < end; ++e) {
        const int c0 = g_scol[e];
        const float4 xv0 = reinterpret_cast<const float4*>(X + (size_t)c0 * C_IN)[lane];
        const float4* wp = reinterpret_cast<const float4*>(g_w8 + (size_t)e * K_FOLDS);
        const float4 wa0 = wp[0], wa1 = wp[1];
        const float wa[K_FOLDS] = {wa0.x, wa0.y, wa0.z, wa0.w, wa1.x, wa1.y, wa1.z, wa1.w};
        ull x0lo, x0hi;
        PACK2(x0lo, xv0.x, xv0.y); PACK2(x0hi, xv0.z, xv0.w);
#pragma unroll
        for (int k = 0; k < K_FOLDS; k++) {
            ull wk0;
            PACK2(wk0, wa[k], wa[k]);
            FFMA2(acc[k][0], wk0, x0lo);
            FFMA2(acc[k][1], wk0, x0hi);
        }
    }

    __nv_bfloat162* yh = reinterpret_cast<__nv_bfloat162*>(g_Yh + (size_t)r * KTOT);
    __nv_bfloat162* yl = reinterpret_cast<__nv_bfloat162*>(g_Yl + (size_t)r * KTOT);
#pragma unroll
    for (int k = 0; k < K_FOLDS; k++) {
        float v[4];
        UNPACK2(v[0], v[1], acc[k][0]);
        UNPACK2(v[2], v[3], acc[k][1]);
        __nv_bfloat16 h[4], l[4];
#pragma unroll
        for (int j = 0; j < 4; j++) {
            h[j] = __float2bfloat16(v[j]);
            l[j] = __float2bfloat16(v[j] - __bfloat162float(h[j]));
        }
        const int o = k * (C_IN / 2) + lane * 2;
        yh[o]     = __halves2bfloat162(h[0], h[1]);
        yh[o + 1] = __halves2bfloat162(h[2], h[3]);
        yl[o]     = __halves2bfloat162(l[0], l[1]);
        yl[o + 1] = __halves2bfloat162(l[2], l[3]);
    }
}

// ---------------------------------------------------------------------------
// gemm_mma (R9 config): out = Yh@Wth + Yh@Wtl + Yl@Wth + bias
// CTA: 64 M-rows x 128 N. 8 warps (2M x 4N), warp tile 32x32.
// K=1024 in 16 stages of 64; cp.async double buffer (96 KB, 2 CTAs/SM).
// ---------------------------------------------------------------------------
#define STG_BYTES 49152
#define SM_AH 0
#define SM_AL 8192
#define SM_BH 16384
#define SM_BL 32768
#define GEMM_SMEM (2 * STG_BYTES)

#define CPA(dst, src) asm volatile("cp.async.cg.shared.global [%0], [%1], 16;" \
                                   :: "r"(dst), "l"(src) : "memory")
#define CPC()  asm volatile("cp.async.commit_group;" ::: "memory")
#define CPW1() asm volatile("cp.async.wait_group 1;" ::: "memory")
#define CPW0() asm volatile("cp.async.wait_group 0;" ::: "memory")

#define LDSM4(r, addr)                                                            \
    asm volatile("ldmatrix.sync.aligned.m8n8.x4.shared.b16 {%0,%1,%2,%3}, [%4];"  \
        : "=r"((r)[0]), "=r"((r)[1]), "=r"((r)[2]), "=r"((r)[3]) : "r"(addr))

#define MMA_BF16(c, a, b0, b1)                                                    \
    asm volatile("mma.sync.aligned.m16n8k16.row.col.f32.bf16.bf16.f32 "           \
        "{%0,%1,%2,%3}, {%4,%5,%6,%7}, {%8,%9}, {%0,%1,%2,%3};"                   \
        : "+f"((c)[0]), "+f"((c)[1]), "+f"((c)[2]), "+f"((c)[3])                  \
        : "r"((a)[0]), "r"((a)[1]), "r"((a)[2]), "r"((a)[3]), "r"(b0), "r"(b1))

__global__ __launch_bounds__(256, 2) void gemm_mma(const float* __restrict__ bias,
                                                   float* __restrict__ out) {
    extern __shared__ char dynsm[];
    __shared__ float s_bias[FILTERS];

    const int tid  = threadIdx.x;
    const int lane = tid & 31;
    const int wid  = tid >> 5;
    const int mb   = blockIdx.x;

    if (tid < FILTERS) s_bias[tid] = bias[tid];

    const int wm = wid >> 2;
    const int wn = wid & 3;

    const uint32_t smbase = smem_u32(dynsm);

    const int ra = tid >> 2;
    const int ca = (tid & 3) * 32;
    const int rb = tid >> 1;
    const int cbb = (tid & 1) * 64;
    const int ga_row = min(mb * 64 + ra, N_NODES - 1);
    const char* gYh = reinterpret_cast<const char*>(g_Yh + (size_t)ga_row * KTOT);
    const char* gYl = reinterpret_cast<const char*>(g_Yl + (size_t)ga_row * KTOT);
    const char* gWh = reinterpret_cast<const char*>(g_Wth + (size_t)rb * KTOT);
    const char* gWl = reinterpret_cast<const char*>(g_Wtl + (size_t)rb * KTOT);
    const uint32_t saoff0 = SW128((uint32_t)(ra * 128 + ca));
    const uint32_t saoff1 = SW128((uint32_t)(ra * 128 + ca + 16));
    uint32_t sboff[4];
#pragma unroll
    for (int i = 0; i < 4; i++) sboff[i] = SW128((uint32_t)(rb * 128 + cbb + i * 16));

    const int trow = lane & 7;
    const int bit3 = (lane >> 3) & 1;
    const int bit4 = (lane >> 4) & 1;
    const int am60 = (trow << 4) & 0x60;
    const int am10 = (trow << 4) & 0x10;
    const int arow = trow + bit3 * 8;
    const int acol0 = (bit4 * 16) ^ am10;
    const int brow = trow + bit4 * 8;
    const int bcol0 = (bit3 * 16) ^ am10;

    uint32_t aoff[2], boff[2];
#pragma unroll
    for (int mi = 0; mi < 2; mi++)
        aoff[mi] = (uint32_t)((wm * 32 + mi * 16 + arow) * 128 + acol0);
#pragma unroll
    for (int nj = 0; nj < 2; nj++)
        boff[nj] = (uint32_t)((wn * 32 + nj * 16 + brow) * 128 + bcol0);

    float acc[2][4][4];
#pragma unroll
    for (int mi = 0; mi < 2; mi++)
#pragma unroll
        for (int ni = 0; ni < 4; ni++)
#pragma unroll
            for (int j = 0; j < 4; j++) acc[mi][ni][j] = 0.0f;

    {
        const uint32_t sb = smbase;
        CPA(sb + SM_AH + saoff0, gYh + ca);
        CPA(sb + SM_AH + saoff1, gYh + ca + 16);
        CPA(sb + SM_AL + saoff0, gYl + ca);
        CPA(sb + SM_AL + saoff1, gYl + ca + 16);
#pragma unroll
        for (int i = 0; i < 4; i++) {
            CPA(sb + SM_BH + sboff[i], gWh + cbb + i * 16);
            CPA(sb + SM_BL + sboff[i], gWl + cbb + i * 16);
        }
        CPC();
    }

    for (int s = 0; s < 16; ++s) {
        if (s < 15) {
            const uint32_t sb = smbase + (uint32_t)(((s + 1) & 1) * STG_BYTES);
            const int kb = (s + 1) * 128;
            CPA(sb + SM_AH + saoff0, gYh + kb + ca);
            CPA(sb + SM_AH + saoff1, gYh + kb + ca + 16);
            CPA(sb + SM_AL + saoff0, gYl + kb + ca);
            CPA(sb + SM_AL + saoff1, gYl + kb + ca + 16);
#pragma unroll
            for (int i = 0; i < 4; i++) {
                CPA(sb + SM_BH + sboff[i], gWh + kb + cbb + i * 16);
                CPA(sb + SM_BL + sboff[i], gWl + kb + cbb + i * 16);
            }
            CPC();
            CPW1();
        } else {
            CPW0();
        }
        __syncthreads();

        const uint32_t cb = smbase + (uint32_t)((s & 1) * STG_BYTES);
        const uint32_t sAh = cb + SM_AH, sAl = cb + SM_AL;
        const uint32_t sBh = cb + SM_BH, sBl = cb + SM_BL;

#pragma unroll
        for (int ks = 0; ks < 4; ++ks) {
            const uint32_t kx = (uint32_t)((ks * 32) ^ am60);
            uint32_t ah[2][4], al[2][4], bh[2][4], bl[2][4];
            LDSM4(ah[0], sAh + aoff[0] + kx);
            LDSM4(ah[1], sAh + aoff[1] + kx);
            LDSM4(al[0], sAl + aoff[0] + kx);
            LDSM4(al[1], sAl + aoff[1] + kx);
            LDSM4(bh[0], sBh + boff[0] + kx);
            LDSM4(bh[1], sBh + boff[1] + kx);
            LDSM4(bl[0], sBl + boff[0] + kx);
            LDSM4(bl[1], sBl + boff[1] + kx);
#pragma unroll
            for (int ni = 0; ni < 4; ++ni) {
                const uint32_t b0h = bh[ni >> 1][(ni & 1) * 2];
                const uint32_t b1h = bh[ni >> 1][(ni & 1) * 2 + 1];
                const uint32_t b0l = bl[ni >> 1][(ni & 1) * 2];
                const uint32_t b1l = bl[ni >> 1][(ni & 1) * 2 + 1];
                MMA_BF16(acc[0][ni], ah[0], b0h, b1h);
                MMA_BF16(acc[1][ni], ah[1], b0h, b1h);
                MMA_BF16(acc[0][ni], ah[0], b0l, b1l);
                MMA_BF16(acc[1][ni], ah[1], b0l, b1l);
                MMA_BF16(acc[0][ni], al[0], b0h, b1h);
                MMA_BF16(acc[1][ni], al[1], b0h, b1h);
            }
        }
        __syncthreads();
    }

    const int g   = lane >> 2;
    const int tig = lane & 3;
#pragma unroll
    for (int mi = 0; mi < 2; ++mi) {
        const int r0 = mb * 64 + wm * 32 + mi * 16 + g;
#pragma unroll
        for (int ni = 0; ni < 4; ++ni) {
            const int c0 = wn * 32 + ni * 8 + tig * 2;
            const float2 bb = *reinterpret_cast<const float2*>(&s_bias[c0]);
            if (r0 < N_NODES) {
                float2 v = make_float2(acc[mi][ni][0] + bb.x, acc[mi][ni][1] + bb.y);
                *reinterpret_cast<float2*>(out + (size_t)r0 * FILTERS + c0) = v;
            }
            if (r0 + 8 < N_NODES) {
                float2 v = make_float2(acc[mi][ni][2] + bb.x, acc[mi][ni][3] + bb.y);
                *reinterpret_cast<float2*>(out + (size_t)(r0 + 8) * FILTERS + c0) = v;
            }
        }
    }
}

// ---------------------------------------------------------------------------
extern "C" void kernel_launch(void* const* d_in, const int* in_sizes, int n_in,
                              void* d_out, int out_size) {
    const float* X    = (const float*)d_in[0];   // node_features (20000,128)
    const float* ef   = (const float*)d_in[1];   // edge_features (8,640000)
    const float* Wall = (const float*)d_in[2];   // kernel (8,128,128)
    const float* bias = (const float*)d_in[3];   // bias (128,)
    const int*   idx  = (const int*)d_in[4];     // indices (640000,2) int32
    float*       out  = (float*)d_out;           // (20000,128)

    cudaFuncSetAttribute(gemm_mma, cudaFuncAttributeMaxDynamicSharedMemorySize, GEMM_SMEM);
    cudaFuncSetAttribute(scan_hist, cudaFuncAttributeMaxDynamicSharedMemorySize, SCAN_SMEM);

    hist_prep<<<N_EDGES / 256, 256>>>(idx, Wall);
    scan_hist<<<1, 1024, SCAN_SMEM>>>();
    scatter_sort<<<N_EDGES / 256, 256>>>(idx, ef);

    row_gather<<<(N_NODES + 7) / 8, 256>>>(X);

    gemm_mma<<<(N_NODES + 63) / 64, 256, GEMM_SMEM>>>(bias, out);
}